// round 15
// baseline (speedup 1.0000x reference)
#include <cuda_runtime.h>
#include <cuda_bf16.h>
#include <cstdint>
#include <cstddef>

#define N_NODES 100000
#define F_IN 128
#define HID 256
#define E_MAX 1600000
#define B_MAX 16384
#define NBLK_SCAN ((N_NODES + 255) / 256)

// ---------------- scratch (device globals; no allocation allowed) ----------------
__device__ int g_idx64;
__device__ int g_deg[N_NODES];
__device__ int g_bsum[NBLK_SCAN + 1];
__device__ int g_rowstart[N_NODES + 1];
__device__ int g_wptr[N_NODES];
__device__ int g_csr[E_MAX];

__device__ int g_mark[N_NODES];
__device__ int g_node2slot[N_NODES];
__device__ int g_sel[B_MAX];
__device__ int g_nsel;

__device__ __nv_bfloat16 g_xh[(size_t)N_NODES * F_IN];
__device__ __nv_bfloat16 g_xl[(size_t)N_NODES * F_IN];
__device__ __nv_bfloat16 g_a1h[(size_t)N_NODES * F_IN];
__device__ __nv_bfloat16 g_a1l[(size_t)N_NODES * F_IN];
__device__ float         g_h1[(size_t)N_NODES * HID];
__device__ __nv_bfloat16 g_h1ch[(size_t)B_MAX * HID];
__device__ __nv_bfloat16 g_h1cl[(size_t)B_MAX * HID];
__device__ __nv_bfloat16 g_a2h[(size_t)B_MAX * HID];
__device__ __nv_bfloat16 g_a2l[(size_t)B_MAX * HID];
__device__ float         g_h2c[(size_t)B_MAX * HID];

__device__ __nv_bfloat16 g_wl1h[256 * F_IN], g_wl1l[256 * F_IN];
__device__ __nv_bfloat16 g_wr1h[256 * F_IN], g_wr1l[256 * F_IN];
__device__ __nv_bfloat16 g_wl2h[256 * HID], g_wl2l[256 * HID];
__device__ __nv_bfloat16 g_wr2h[256 * HID], g_wr2l[256 * HID];

// ---------------- helpers ----------------
__device__ __forceinline__ void split1(float v, __nv_bfloat16& h, __nv_bfloat16& l) {
    h = __float2bfloat16(v);
    l = __float2bfloat16(v - __bfloat162float(h));
}

__device__ __forceinline__ void split_store4(float4 v, __nv_bfloat16* ph, __nv_bfloat16* pl) {
    __nv_bfloat16 h0, h1, h2, h3, l0, l1, l2, l3;
    split1(v.x, h0, l0); split1(v.y, h1, l1);
    split1(v.z, h2, l2); split1(v.w, h3, l3);
    __nv_bfloat162* H = reinterpret_cast<__nv_bfloat162*>(ph);
    __nv_bfloat162* L = reinterpret_cast<__nv_bfloat162*>(pl);
    H[0] = __halves2bfloat162(h0, h1);
    H[1] = __halves2bfloat162(h2, h3);
    L[0] = __halves2bfloat162(l0, l1);
    L[1] = __halves2bfloat162(l2, l3);
}

__device__ __forceinline__ uint32_t smem_to_u32(const void* smem_ptr) {
    uint32_t addr;
    asm("{ .reg .u64 tmp; cvta.to.shared.u64 tmp, %1; cvt.u32.u64 %0, tmp; }"
        : "=r"(addr) : "l"(smem_ptr));
    return addr;
}

__device__ __forceinline__ void ldsm_x4(uint32_t* r, uint32_t a) {
    asm volatile("ldmatrix.sync.aligned.m8n8.x4.shared.b16 {%0,%1,%2,%3}, [%4];"
                 : "=r"(r[0]), "=r"(r[1]), "=r"(r[2]), "=r"(r[3]) : "r"(a));
}

__device__ __forceinline__ void cp_async16(uint32_t dst, const void* src, int srcsize) {
    asm volatile("cp.async.ca.shared.global [%0], [%1], 16, %2;"
                 :: "r"(dst), "l"(src), "r"(srcsize));
}
#define CP_COMMIT() asm volatile("cp.async.commit_group;" ::: "memory")
#define CP_WAIT1() asm volatile("cp.async.wait_group 1;" ::: "memory")
#define CP_WAIT0() asm volatile("cp.async.wait_group 0;" ::: "memory")

// ---------------- index dtype sniff (parallel: 32 lanes x 2 entries) ----------------
__global__ void sniff_kernel(const int* __restrict__ e) {
    int lane = threadIdx.x & 31;
    int nz = 0;
    if (e[2 * lane + 1] != 0) nz = 1;
    if (e[2 * (lane + 32) + 1] != 0) nz = 1;
    unsigned any = __ballot_sync(0xffffffffu, nz);
    if (lane == 0) g_idx64 = (any == 0u) ? 1 : 0;
}

__device__ __forceinline__ int load_idx(const void* __restrict__ p, size_t i, int is64) {
    if (is64) return (int)((const long long*)p)[i];
    return ((const int*)p)[i];
}

// ---------------- CSR build ----------------
__global__ void zero_deg_mark_kernel() {
    int i = blockIdx.x * blockDim.x + threadIdx.x;
    if (i < N_NODES) {
        g_deg[i] = 0;
        g_mark[i] = 0;
    }
    if (i == 0) g_nsel = 0;
}

__global__ void degree_kernel(const void* __restrict__ edge, int E) {
    int e = blockIdx.x * blockDim.x + threadIdx.x;
    if (e >= E) return;
    int d = load_idx(edge, (size_t)E + e, g_idx64);
    atomicAdd(&g_deg[d], 1);
}

__global__ void blocksum_kernel() {
    __shared__ int ws[8];
    int i = blockIdx.x * 256 + threadIdx.x;
    int v = (i < N_NODES) ? g_deg[i] : 0;
    int lane = threadIdx.x & 31, wid = threadIdx.x >> 5;
#pragma unroll
    for (int o = 16; o; o >>= 1) v += __shfl_down_sync(0xffffffffu, v, o);
    if (lane == 0) ws[wid] = v;
    __syncthreads();
    if (threadIdx.x == 0) {
        int s = 0;
#pragma unroll
        for (int k = 0; k < 8; k++) s += ws[k];
        g_bsum[blockIdx.x] = s;
    }
}

__global__ __launch_bounds__(512) void scan_bsum_kernel(int E) {
    __shared__ int wsum[16];
    int tid = threadIdx.x, lane = tid & 31, wid = tid >> 5;
    int v = (tid < NBLK_SCAN) ? g_bsum[tid] : 0;
    int s = v;
#pragma unroll
    for (int o = 1; o < 32; o <<= 1) {
        int t = __shfl_up_sync(0xffffffffu, s, o);
        if (lane >= o) s += t;
    }
    if (lane == 31) wsum[wid] = s;
    __syncthreads();
    if (wid == 0 && lane < 16) {
        int ws = wsum[lane];
        int ss = ws;
#pragma unroll
        for (int o = 1; o < 16; o <<= 1) {
            int t = __shfl_up_sync(0xffffu, ss, o);
            if (lane >= o) ss += t;
        }
        wsum[lane] = ss;
    }
    __syncthreads();
    int excl = s - v + (wid ? wsum[wid - 1] : 0);
    if (tid < NBLK_SCAN) g_bsum[tid] = excl;
    if (tid == 0) g_rowstart[N_NODES] = E;
}

__global__ void distribute_kernel() {
    __shared__ int wsum[8];
    int tid = threadIdx.x, lane = tid & 31, wid = tid >> 5;
    int i = blockIdx.x * 256 + tid;
    int v = (i < N_NODES) ? g_deg[i] : 0;
    int s = v;
#pragma unroll
    for (int o = 1; o < 32; o <<= 1) {
        int t = __shfl_up_sync(0xffffffffu, s, o);
        if (lane >= o) s += t;
    }
    if (lane == 31) wsum[wid] = s;
    __syncthreads();
    if (wid == 0 && lane < 8) {
        int ws = wsum[lane];
        int ss = ws;
#pragma unroll
        for (int o = 1; o < 8; o <<= 1) {
            int t = __shfl_up_sync(0xffu, ss, o);
            if (lane >= o) ss += t;
        }
        wsum[lane] = ss;
    }
    __syncthreads();
    int excl = s - v + (wid ? wsum[wid - 1] : 0) + g_bsum[blockIdx.x];
    if (i < N_NODES) {
        g_rowstart[i] = excl;
        g_wptr[i] = excl;
    }
}

__global__ void fill_kernel(const void* __restrict__ edge, int E) {
    int e = blockIdx.x * blockDim.x + threadIdx.x;
    if (e >= E) return;
    int is64 = g_idx64;
    int s = load_idx(edge, e, is64);
    int d = load_idx(edge, (size_t)E + e, is64);
    int pos = atomicAdd(&g_wptr[d], 1);
    g_csr[pos] = s;
}

// ---------------- batch node selection ----------------
__global__ void mark_kernel(const void* __restrict__ idx, int B) {
    int r = blockIdx.x * blockDim.x + threadIdx.x;
    if (r >= B) return;
    int node = load_idx(idx, r, g_idx64);
    g_mark[node] = 1;
}

__global__ void compact_kernel() {
    int i = blockIdx.x * blockDim.x + threadIdx.x;
    if (i >= N_NODES) return;
    if (g_mark[i]) {
        int slot = atomicAdd(&g_nsel, 1);
        g_sel[slot] = i;
        g_node2slot[i] = slot;
    }
}

// ---------------- splits ----------------
__global__ void split_x_kernel(const float* __restrict__ x) {
    size_t i = (size_t)blockIdx.x * blockDim.x + threadIdx.x;
    const size_t n4 = (size_t)N_NODES * F_IN / 4;
    if (i >= n4) return;
    float4 v = reinterpret_cast<const float4*>(x)[i];
    split_store4(v, g_xh + i * 4, g_xl + i * 4);
}

__global__ void split_w_kernel(const float* __restrict__ W,
                               __nv_bfloat16* __restrict__ Th,
                               __nv_bfloat16* __restrict__ Tl, int K) {
    int idx = blockIdx.x * blockDim.x + threadIdx.x;
    if (idx >= K * 256) return;
    int k = idx >> 8;
    int n = idx & 255;
    __nv_bfloat16 h, l;
    split1(W[idx], h, l);
    Th[n * K + k] = h;
    Tl[n * K + k] = l;
}

// ---------------- layer-1 aggregate -> bf16 hi/lo (4-edge unroll) ----------------
__global__ __launch_bounds__(256) void agg1_kernel(const float* __restrict__ x) {
    int n = (int)(((size_t)blockIdx.x * blockDim.x + threadIdx.x) >> 5);
    if (n >= N_NODES) return;
    int lane = threadIdx.x & 31;
    int start = g_rowstart[n];
    int end = g_rowstart[n + 1];
    float4 acc0 = make_float4(0.f, 0.f, 0.f, 0.f);
    float4 acc1 = make_float4(0.f, 0.f, 0.f, 0.f);
    float4 acc2 = make_float4(0.f, 0.f, 0.f, 0.f);
    float4 acc3 = make_float4(0.f, 0.f, 0.f, 0.f);
    int e = start;
    for (; e + 3 < end; e += 4) {
        int s0 = g_csr[e];
        int s1 = g_csr[e + 1];
        int s2 = g_csr[e + 2];
        int s3 = g_csr[e + 3];
        float4 v0 = reinterpret_cast<const float4*>(x + (size_t)s0 * F_IN)[lane];
        float4 v1 = reinterpret_cast<const float4*>(x + (size_t)s1 * F_IN)[lane];
        float4 v2 = reinterpret_cast<const float4*>(x + (size_t)s2 * F_IN)[lane];
        float4 v3 = reinterpret_cast<const float4*>(x + (size_t)s3 * F_IN)[lane];
        acc0.x += v0.x; acc0.y += v0.y; acc0.z += v0.z; acc0.w += v0.w;
        acc1.x += v1.x; acc1.y += v1.y; acc1.z += v1.z; acc1.w += v1.w;
        acc2.x += v2.x; acc2.y += v2.y; acc2.z += v2.z; acc2.w += v2.w;
        acc3.x += v3.x; acc3.y += v3.y; acc3.z += v3.z; acc3.w += v3.w;
    }
    for (; e < end; e++) {
        int s0 = g_csr[e];
        float4 v0 = reinterpret_cast<const float4*>(x + (size_t)s0 * F_IN)[lane];
        acc0.x += v0.x; acc0.y += v0.y; acc0.z += v0.z; acc0.w += v0.w;
    }
    float r = 1.0f / fmaxf((float)(end - start), 1.0f);
    float4 o;
    o.x = (acc0.x + acc1.x + acc2.x + acc3.x) * r;
    o.y = (acc0.y + acc1.y + acc2.y + acc3.y) * r;
    o.z = (acc0.z + acc1.z + acc2.z + acc3.z) * r;
    o.w = (acc0.w + acc1.w + acc2.w + acc3.w) * r;
    size_t off = (size_t)n * F_IN + lane * 4;
    split_store4(o, g_a1h + off, g_a1l + off);
}

// ---------------- layer-2 aggregate (selected slots) -> bf16 hi/lo (2-edge unroll) ----------------
__global__ __launch_bounds__(256) void agg2c_kernel() {
    int slot = (int)(((size_t)blockIdx.x * blockDim.x + threadIdx.x) >> 5);
    if (slot >= g_nsel) return;
    int n = g_sel[slot];
    int lane = threadIdx.x & 31;
    int start = g_rowstart[n];
    int end = g_rowstart[n + 1];
    float4 a0 = make_float4(0.f, 0.f, 0.f, 0.f);
    float4 a1 = make_float4(0.f, 0.f, 0.f, 0.f);
    float4 b0 = make_float4(0.f, 0.f, 0.f, 0.f);
    float4 b1 = make_float4(0.f, 0.f, 0.f, 0.f);
    int e = start;
    for (; e + 1 < end; e += 2) {
        int s0 = g_csr[e];
        int s1 = g_csr[e + 1];
        const float4* hp0 = reinterpret_cast<const float4*>(g_h1 + (size_t)s0 * HID);
        const float4* hp1 = reinterpret_cast<const float4*>(g_h1 + (size_t)s1 * HID);
        float4 u0 = hp0[lane];
        float4 u1 = hp0[lane + 32];
        float4 w0 = hp1[lane];
        float4 w1 = hp1[lane + 32];
        a0.x += u0.x; a0.y += u0.y; a0.z += u0.z; a0.w += u0.w;
        a1.x += u1.x; a1.y += u1.y; a1.z += u1.z; a1.w += u1.w;
        b0.x += w0.x; b0.y += w0.y; b0.z += w0.z; b0.w += w0.w;
        b1.x += w1.x; b1.y += w1.y; b1.z += w1.z; b1.w += w1.w;
    }
    if (e < end) {
        int s0 = g_csr[e];
        const float4* hp0 = reinterpret_cast<const float4*>(g_h1 + (size_t)s0 * HID);
        float4 u0 = hp0[lane];
        float4 u1 = hp0[lane + 32];
        a0.x += u0.x; a0.y += u0.y; a0.z += u0.z; a0.w += u0.w;
        a1.x += u1.x; a1.y += u1.y; a1.z += u1.z; a1.w += u1.w;
    }
    float r = 1.0f / fmaxf((float)(end - start), 1.0f);
    a0.x = (a0.x + b0.x) * r; a0.y = (a0.y + b0.y) * r;
    a0.z = (a0.z + b0.z) * r; a0.w = (a0.w + b0.w) * r;
    a1.x = (a1.x + b1.x) * r; a1.y = (a1.y + b1.y) * r;
    a1.z = (a1.z + b1.z) * r; a1.w = (a1.w + b1.w) * r;
    size_t off = (size_t)slot * HID;
    split_store4(a0, g_a2h + off + lane * 4, g_a2l + off + lane * 4);
    split_store4(a1, g_a2h + off + 128 + lane * 4, g_a2l + off + 128 + lane * 4);
}

// ---------------- bf16x2 tensor-core dual GEMM: cp.async double-buffer + ldmatrix ----------------
__device__ __forceinline__ void mma_bf16(float* c, const uint32_t* a, const uint32_t* b) {
    asm volatile(
        "mma.sync.aligned.m16n8k16.row.col.f32.bf16.bf16.f32 "
        "{%0,%1,%2,%3}, {%4,%5,%6,%7}, {%8,%9}, {%0,%1,%2,%3};"
        : "+f"(c[0]), "+f"(c[1]), "+f"(c[2]), "+f"(c[3])
        : "r"(a[0]), "r"(a[1]), "r"(a[2]), "r"(a[3]), "r"(b[0]), "r"(b[1]));
}

#define GROWB 80
#define GAB 10240
#define GBUFB 40960
#define GEMM_SMEM 81920

__global__ __launch_bounds__(256, 2) void gemm_dual_pre_kernel(
    const __nv_bfloat16* __restrict__ A0h, const __nv_bfloat16* __restrict__ A0l, int K0,
    const __nv_bfloat16* __restrict__ A1h, const __nv_bfloat16* __restrict__ A1l, int K1,
    const __nv_bfloat16* __restrict__ B0h, const __nv_bfloat16* __restrict__ B0l,
    const __nv_bfloat16* __restrict__ B1h, const __nv_bfloat16* __restrict__ B1l,
    const float* __restrict__ bias, float* __restrict__ C,
    __nv_bfloat16* __restrict__ Ch, __nv_bfloat16* __restrict__ Cl, int M) {
    const int N = 256;
    extern __shared__ char gsm[];
    uint32_t sbase = smem_to_u32(gsm);

    int tid = threadIdx.x;
    int lane = tid & 31;
    int wid = tid >> 5;
    int bm = blockIdx.x * 128;
    int bn = blockIdx.y * 128;
    int wm = (wid >> 2) * 64;
    int wn = (wid & 3) * 32;

    float acc[4][4][4];
#pragma unroll
    for (int mi = 0; mi < 4; mi++)
#pragma unroll
        for (int ni = 0; ni < 4; ni++)
#pragma unroll
            for (int q = 0; q < 4; q++) acc[mi][ni][q] = 0.f;

    int arow = tid >> 1;
    int ak0 = (tid & 1) * 16;
    int g = lane >> 2;
    int tq = (lane & 3) * 2;

    int lrA = lane & 15;
    int lcA = (lane >> 4) << 3;
    int lrBoff = ((lane >> 4) << 3) + (lane & 7);
    int lcB = ((lane >> 3) & 1) << 3;

    int K = K0 + K1;
    int T = K >> 5;

    int asz = (bm + arow < M) ? 16 : 0;
    uint32_t sA = sbase + arow * GROWB + ak0 * 2;
    uint32_t sB = sbase + 2 * GAB + arow * GROWB + ak0 * 2;

    auto issue = [&](int t, int buf) {
        const __nv_bfloat16 *pah, *pal, *pbh, *pbl;
        int lda, kloc;
        int kt = t << 5;
        if (kt < K0) { pah = A0h; pal = A0l; pbh = B0h; pbl = B0l; lda = K0; kloc = kt; }
        else         { pah = A1h; pal = A1l; pbh = B1h; pbl = B1l; lda = K1; kloc = kt - K0; }
        size_t aoff = (size_t)(bm + arow) * lda + kloc + ak0;
        size_t boff = (size_t)(bn + arow) * lda + kloc + ak0;
        uint32_t bofs = buf * GBUFB;
        cp_async16(sA + bofs, pah + aoff, asz);
        cp_async16(sA + bofs + 16, pah + aoff + 8, asz);
        cp_async16(sA + bofs + GAB, pal + aoff, asz);
        cp_async16(sA + bofs + GAB + 16, pal + aoff + 8, asz);
        cp_async16(sB + bofs, pbh + boff, 16);
        cp_async16(sB + bofs + 16, pbh + boff + 8, 16);
        cp_async16(sB + bofs + GAB, pbl + boff, 16);
        cp_async16(sB + bofs + GAB + 16, pbl + boff + 8, 16);
    };

    issue(0, 0); CP_COMMIT();
    if (T > 1) { issue(1, 1); CP_COMMIT(); }

    for (int t = 0; t < T; t++) {
        if (t == T - 1) { CP_WAIT0(); } else { CP_WAIT1(); }
        __syncthreads();

        int buf = t & 1;
        uint32_t bb = sbase + buf * GBUFB;
#pragma unroll
        for (int ks = 0; ks < 2; ks++) {
            int k0 = ks * 16;
            uint32_t bfh[4][2], bfl[4][2];
#pragma unroll
            for (int np = 0; np < 4; np += 2) {
                uint32_t aB = bb + 2 * GAB + (wn + np * 8 + lrBoff) * GROWB + (k0 + lcB) * 2;
                uint32_t r[4];
                ldsm_x4(r, aB);
                bfh[np][0] = r[0]; bfh[np][1] = r[1];
                bfh[np + 1][0] = r[2]; bfh[np + 1][1] = r[3];
                ldsm_x4(r, aB + GAB);
                bfl[np][0] = r[0]; bfl[np][1] = r[1];
                bfl[np + 1][0] = r[2]; bfl[np + 1][1] = r[3];
            }
            uint32_t aA = bb + (wm + lrA) * GROWB + (k0 + lcA) * 2;
#pragma unroll
            for (int mi = 0; mi < 4; mi++) {
                uint32_t ah[4], al[4];
                ldsm_x4(ah, aA + mi * (16 * GROWB));
                ldsm_x4(al, aA + GAB + mi * (16 * GROWB));
#pragma unroll
                for (int ni = 0; ni < 4; ni++) {
                    mma_bf16(acc[mi][ni], ah, bfh[ni]);
                    mma_bf16(acc[mi][ni], ah, bfl[ni]);
                    mma_bf16(acc[mi][ni], al, bfh[ni]);
                }
            }
        }
        __syncthreads();
        if (t + 2 < T) { issue(t + 2, buf); CP_COMMIT(); }
    }

#pragma unroll
    for (int mi = 0; mi < 4; mi++) {
#pragma unroll
        for (int ni = 0; ni < 4; ni++) {
            int col = bn + wn + ni * 8 + tq;
            float bv0 = bias[col];
            float bv1 = bias[col + 1];
#pragma unroll
            for (int h = 0; h < 2; h++) {
                int r = bm + wm + mi * 16 + g + h * 8;
                if (r < M) {
                    float v0 = fmaxf(acc[mi][ni][h * 2 + 0] + bv0, 0.f);
                    float v1 = fmaxf(acc[mi][ni][h * 2 + 1] + bv1, 0.f);
                    *reinterpret_cast<float2*>(&C[(size_t)r * N + col]) = make_float2(v0, v1);
                    if (Ch && g_mark[r]) {
                        int slot = g_node2slot[r];
                        __nv_bfloat16 h0, h1, l0, l1;
                        split1(v0, h0, l0);
                        split1(v1, h1, l1);
                        *reinterpret_cast<__nv_bfloat162*>(&Ch[(size_t)slot * N + col]) =
                            __halves2bfloat162(h0, h1);
                        *reinterpret_cast<__nv_bfloat162*>(&Cl[(size_t)slot * N + col]) =
                            __halves2bfloat162(l0, l1);
                    }
                }
            }
        }
    }
}

// ---------------- MLP head ----------------
__global__ __launch_bounds__(256) void mlp_kernel(
    const float* __restrict__ x_tab, const void* __restrict__ idx,
    const float* __restrict__ W1, const float* __restrict__ b1,
    const float* __restrict__ W2, const float* __restrict__ b2,
    const float* __restrict__ W3, const float* __restrict__ b3,
    float* __restrict__ out, int B) {
    __shared__ float zs[8][280];
    __shared__ float z1s[8][64];
    int w = threadIdx.x >> 5;
    int lane = threadIdx.x & 31;
    int row = blockIdx.x * 8 + w;
    if (row >= B) return;
    int node = load_idx(idx, row, g_idx64);
    int slot = g_node2slot[node];
    const float4* h = reinterpret_cast<const float4*>(g_h2c + (size_t)slot * HID);
    float4 v = h[lane];
    *reinterpret_cast<float4*>(&zs[w][lane * 4]) = v;
    v = h[lane + 32];
    *reinterpret_cast<float4*>(&zs[w][128 + lane * 4]) = v;
    if (lane < 16) zs[w][256 + lane] = x_tab[row * 16 + lane];
    __syncwarp();

    float a0 = b1[lane];
    float a1 = b1[lane + 32];
#pragma unroll 4
    for (int k = 0; k < 272; k++) {
        float zk = zs[w][k];
        a0 += zk * W1[k * 64 + lane];
        a1 += zk * W1[k * 64 + lane + 32];
    }
    z1s[w][lane] = fmaxf(a0, 0.f);
    z1s[w][lane + 32] = fmaxf(a1, 0.f);
    __syncwarp();

    float a = b2[lane];
#pragma unroll
    for (int k = 0; k < 64; k++) a += z1s[w][k] * W2[k * 32 + lane];
    float z2 = fmaxf(a, 0.f);

    float p = z2 * W3[lane];
#pragma unroll
    for (int off = 16; off; off >>= 1) p += __shfl_down_sync(0xffffffffu, p, off);
    if (lane == 0) out[row] = p + b3[0];
}

// ---------------- launch ----------------
extern "C" void kernel_launch(void* const* d_in, const int* in_sizes, int n_in,
                              void* d_out, int out_size) {
    const float* x     = (const float*)d_in[0];
    const void* edge   = d_in[1];
    const void* idxb   = d_in[2];
    const float* x_tab = (const float*)d_in[3];
    const float* Wl1 = (const float*)d_in[4];
    const float* bl1 = (const float*)d_in[5];
    const float* Wr1 = (const float*)d_in[6];
    const float* Wl2 = (const float*)d_in[7];
    const float* bl2 = (const float*)d_in[8];
    const float* Wr2 = (const float*)d_in[9];
    const float* W1  = (const float*)d_in[10];
    const float* b1  = (const float*)d_in[11];
    const float* W2  = (const float*)d_in[12];
    const float* b2  = (const float*)d_in[13];
    const float* W3  = (const float*)d_in[14];
    const float* b3  = (const float*)d_in[15];
    float* out = (float*)d_out;

    int E = in_sizes[1] / 2;
    if (E > E_MAX) E = E_MAX;
    int B = in_sizes[2];
    if (B > B_MAX) B = B_MAX;

    __nv_bfloat16 *p_xh, *p_xl, *p_a1h, *p_a1l, *p_h1ch, *p_h1cl, *p_a2h, *p_a2l;
    __nv_bfloat16 *p_wl1h, *p_wl1l, *p_wr1h, *p_wr1l, *p_wl2h, *p_wl2l, *p_wr2h, *p_wr2l;
    float *p_h1, *p_h2c;
    cudaGetSymbolAddress((void**)&p_xh, g_xh);
    cudaGetSymbolAddress((void**)&p_xl, g_xl);
    cudaGetSymbolAddress((void**)&p_a1h, g_a1h);
    cudaGetSymbolAddress((void**)&p_a1l, g_a1l);
    cudaGetSymbolAddress((void**)&p_h1, g_h1);
    cudaGetSymbolAddress((void**)&p_h1ch, g_h1ch);
    cudaGetSymbolAddress((void**)&p_h1cl, g_h1cl);
    cudaGetSymbolAddress((void**)&p_a2h, g_a2h);
    cudaGetSymbolAddress((void**)&p_a2l, g_a2l);
    cudaGetSymbolAddress((void**)&p_h2c, g_h2c);
    cudaGetSymbolAddress((void**)&p_wl1h, g_wl1h);
    cudaGetSymbolAddress((void**)&p_wl1l, g_wl1l);
    cudaGetSymbolAddress((void**)&p_wr1h, g_wr1h);
    cudaGetSymbolAddress((void**)&p_wr1l, g_wr1l);
    cudaGetSymbolAddress((void**)&p_wl2h, g_wl2h);
    cudaGetSymbolAddress((void**)&p_wl2l, g_wl2l);
    cudaGetSymbolAddress((void**)&p_wr2h, g_wr2h);
    cudaGetSymbolAddress((void**)&p_wr2l, g_wr2l);

    static cudaStream_t s1 = nullptr, s2 = nullptr;
    static cudaEvent_t ev_root = nullptr, ev_split = nullptr, ev_sel = nullptr;
    if (!s1) {
        cudaStreamCreateWithFlags(&s1, cudaStreamNonBlocking);
        cudaStreamCreateWithFlags(&s2, cudaStreamNonBlocking);
        cudaEventCreateWithFlags(&ev_root, cudaEventDisableTiming);
        cudaEventCreateWithFlags(&ev_split, cudaEventDisableTiming);
        cudaEventCreateWithFlags(&ev_sel, cudaEventDisableTiming);
        cudaFuncSetAttribute(gemm_dual_pre_kernel,
                             cudaFuncAttributeMaxDynamicSharedMemorySize, GEMM_SMEM);
    }

    // 0. sniff, then fork
    sniff_kernel<<<1, 32>>>((const int*)edge);
    cudaEventRecord(ev_root, 0);
    cudaStreamWaitEvent(s1, ev_root, 0);
    cudaStreamWaitEvent(s2, ev_root, 0);

    // branch A (default): CSR build
    zero_deg_mark_kernel<<<NBLK_SCAN, 256>>>();
    degree_kernel<<<(E + 255) / 256, 256>>>(edge, E);
    blocksum_kernel<<<NBLK_SCAN, 256>>>();
    scan_bsum_kernel<<<1, 512>>>(E);
    distribute_kernel<<<NBLK_SCAN, 256>>>();
    fill_kernel<<<(E + 255) / 256, 256>>>(edge, E);

    // branch B (s1): splits
    {
        size_t n4 = (size_t)N_NODES * F_IN / 4;
        split_x_kernel<<<(int)((n4 + 255) / 256), 256, 0, s1>>>(x);
        split_w_kernel<<<(F_IN * 256 + 255) / 256, 256, 0, s1>>>(Wl1, p_wl1h, p_wl1l, F_IN);
        split_w_kernel<<<(F_IN * 256 + 255) / 256, 256, 0, s1>>>(Wr1, p_wr1h, p_wr1l, F_IN);
        split_w_kernel<<<(HID * 256 + 255) / 256, 256, 0, s1>>>(Wl2, p_wl2h, p_wl2l, HID);
        split_w_kernel<<<(HID * 256 + 255) / 256, 256, 0, s1>>>(Wr2, p_wr2h, p_wr2l, HID);
        cudaEventRecord(ev_split, s1);
    }

    // branch C (s2): batch-node selection (mark/node2slot read by gemm1 epilogue)
    mark_kernel<<<(B + 255) / 256, 256, 0, s2>>>(idxb, B);
    compact_kernel<<<NBLK_SCAN, 256, 0, s2>>>();
    cudaEventRecord(ev_sel, s2);

    // default: layer-1 aggregate (needs CSR only)
    agg1_kernel<<<(N_NODES * 32 + 255) / 256, 256>>>(x);

    // join splits + selection, then gemm1 (fused compacted h1 split)
    cudaStreamWaitEvent(0, ev_split, 0);
    cudaStreamWaitEvent(0, ev_sel, 0);
    {
        dim3 grid((N_NODES + 127) / 128, 2);
        gemm_dual_pre_kernel<<<grid, 256, GEMM_SMEM>>>(
            p_a1h, p_a1l, F_IN, p_xh, p_xl, F_IN,
            p_wl1h, p_wl1l, p_wr1h, p_wr1l,
            bl1, p_h1, p_h1ch, p_h1cl, N_NODES);
    }

    // layer-2 aggregate (selected slots)
    agg2c_kernel<<<(B * 32 + 255) / 256, 256>>>();

    // gemm2 (selected slots)
    {
        dim3 grid((B + 127) / 128, 2);
        gemm_dual_pre_kernel<<<grid, 256, GEMM_SMEM>>>(
            p_a2h, p_a2l, HID, p_h1ch, p_h1cl, HID,
            p_wl2h, p_wl2l, p_wr2h, p_wr2l,
            bl2, p_h2c, (__nv_bfloat16*)nullptr, (__nv_bfloat16*)nullptr, B);
    }

    // MLP head
    mlp_kernel<<<(B + 7) / 8, 256>>>(x_tab, idxb, W1, b1, W2, b2, W3, b3, out, B);
}

// round 16
// speedup vs baseline: 1.0168x; 1.0168x over previous
#include <cuda_runtime.h>
#include <cuda_bf16.h>
#include <cstdint>
#include <cstddef>

#define N_NODES 100000
#define F_IN 128
#define HID 256
#define E_MAX 1600000
#define B_MAX 16384
#define NBLK_SCAN ((N_NODES + 255) / 256)

// ---------------- scratch (device globals; no allocation allowed) ----------------
__device__ int g_idx64;
__device__ int g_deg[N_NODES];
__device__ int g_bsum[NBLK_SCAN + 1];
__device__ int g_rowstart[N_NODES + 1];
__device__ int g_wptr[N_NODES];
__device__ int g_csr[E_MAX];

__device__ int g_mark[N_NODES];
__device__ int g_node2slot[N_NODES];
__device__ int g_sel[B_MAX];
__device__ int g_nsel;

__device__ __nv_bfloat16 g_xh[(size_t)N_NODES * F_IN];
__device__ __nv_bfloat16 g_xl[(size_t)N_NODES * F_IN];
__device__ __nv_bfloat16 g_a1h[(size_t)N_NODES * F_IN];
__device__ __nv_bfloat16 g_a1l[(size_t)N_NODES * F_IN];
__device__ float         g_h1[(size_t)N_NODES * HID];
__device__ __nv_bfloat16 g_h1ch[(size_t)B_MAX * HID];
__device__ __nv_bfloat16 g_h1cl[(size_t)B_MAX * HID];
__device__ __nv_bfloat16 g_a2h[(size_t)B_MAX * HID];
__device__ __nv_bfloat16 g_a2l[(size_t)B_MAX * HID];
__device__ float         g_h2c[(size_t)B_MAX * HID];

__device__ __nv_bfloat16 g_wl1h[256 * F_IN], g_wl1l[256 * F_IN];
__device__ __nv_bfloat16 g_wr1h[256 * F_IN], g_wr1l[256 * F_IN];
__device__ __nv_bfloat16 g_wl2h[256 * HID], g_wl2l[256 * HID];
__device__ __nv_bfloat16 g_wr2h[256 * HID], g_wr2l[256 * HID];

// ---------------- helpers ----------------
__device__ __forceinline__ void split1(float v, __nv_bfloat16& h, __nv_bfloat16& l) {
    h = __float2bfloat16(v);
    l = __float2bfloat16(v - __bfloat162float(h));
}

__device__ __forceinline__ void split_store4(float4 v, __nv_bfloat16* ph, __nv_bfloat16* pl) {
    __nv_bfloat16 h0, h1, h2, h3, l0, l1, l2, l3;
    split1(v.x, h0, l0); split1(v.y, h1, l1);
    split1(v.z, h2, l2); split1(v.w, h3, l3);
    __nv_bfloat162* H = reinterpret_cast<__nv_bfloat162*>(ph);
    __nv_bfloat162* L = reinterpret_cast<__nv_bfloat162*>(pl);
    H[0] = __halves2bfloat162(h0, h1);
    H[1] = __halves2bfloat162(h2, h3);
    L[0] = __halves2bfloat162(l0, l1);
    L[1] = __halves2bfloat162(l2, l3);
}

__device__ __forceinline__ uint32_t smem_to_u32(const void* smem_ptr) {
    uint32_t addr;
    asm("{ .reg .u64 tmp; cvta.to.shared.u64 tmp, %1; cvt.u32.u64 %0, tmp; }"
        : "=r"(addr) : "l"(smem_ptr));
    return addr;
}

__device__ __forceinline__ void ldsm_x4(uint32_t* r, uint32_t a) {
    asm volatile("ldmatrix.sync.aligned.m8n8.x4.shared.b16 {%0,%1,%2,%3}, [%4];"
                 : "=r"(r[0]), "=r"(r[1]), "=r"(r[2]), "=r"(r[3]) : "r"(a));
}

__device__ __forceinline__ void cp_async16(uint32_t dst, const void* src, int srcsize) {
    asm volatile("cp.async.ca.shared.global [%0], [%1], 16, %2;"
                 :: "r"(dst), "l"(src), "r"(srcsize));
}
#define CP_COMMIT() asm volatile("cp.async.commit_group;" ::: "memory")
#define CP_WAIT1() asm volatile("cp.async.wait_group 1;" ::: "memory")
#define CP_WAIT0() asm volatile("cp.async.wait_group 0;" ::: "memory")

// ---------------- index dtype sniff (parallel: 32 lanes x 2 entries) ----------------
__global__ void sniff_kernel(const int* __restrict__ e) {
    int lane = threadIdx.x & 31;
    int nz = 0;
    if (e[2 * lane + 1] != 0) nz = 1;
    if (e[2 * (lane + 32) + 1] != 0) nz = 1;
    unsigned any = __ballot_sync(0xffffffffu, nz);
    if (lane == 0) g_idx64 = (any == 0u) ? 1 : 0;
}

__device__ __forceinline__ int load_idx(const void* __restrict__ p, size_t i, int is64) {
    if (is64) return (int)((const long long*)p)[i];
    return ((const int*)p)[i];
}

// ---------------- CSR build ----------------
__global__ void zero_deg_mark_kernel() {
    int i = blockIdx.x * blockDim.x + threadIdx.x;
    if (i < N_NODES) {
        g_deg[i] = 0;
        g_mark[i] = 0;
    }
    if (i == 0) g_nsel = 0;
}

__global__ void degree_kernel(const void* __restrict__ edge, int E) {
    int e = blockIdx.x * blockDim.x + threadIdx.x;
    if (e >= E) return;
    int d = load_idx(edge, (size_t)E + e, g_idx64);
    atomicAdd(&g_deg[d], 1);
}

__global__ void blocksum_kernel() {
    __shared__ int ws[8];
    int i = blockIdx.x * 256 + threadIdx.x;
    int v = (i < N_NODES) ? g_deg[i] : 0;
    int lane = threadIdx.x & 31, wid = threadIdx.x >> 5;
#pragma unroll
    for (int o = 16; o; o >>= 1) v += __shfl_down_sync(0xffffffffu, v, o);
    if (lane == 0) ws[wid] = v;
    __syncthreads();
    if (threadIdx.x == 0) {
        int s = 0;
#pragma unroll
        for (int k = 0; k < 8; k++) s += ws[k];
        g_bsum[blockIdx.x] = s;
    }
}

__global__ __launch_bounds__(512) void scan_bsum_kernel(int E) {
    __shared__ int wsum[16];
    int tid = threadIdx.x, lane = tid & 31, wid = tid >> 5;
    int v = (tid < NBLK_SCAN) ? g_bsum[tid] : 0;
    int s = v;
#pragma unroll
    for (int o = 1; o < 32; o <<= 1) {
        int t = __shfl_up_sync(0xffffffffu, s, o);
        if (lane >= o) s += t;
    }
    if (lane == 31) wsum[wid] = s;
    __syncthreads();
    if (wid == 0 && lane < 16) {
        int ws = wsum[lane];
        int ss = ws;
#pragma unroll
        for (int o = 1; o < 16; o <<= 1) {
            int t = __shfl_up_sync(0xffffu, ss, o);
            if (lane >= o) ss += t;
        }
        wsum[lane] = ss;
    }
    __syncthreads();
    int excl = s - v + (wid ? wsum[wid - 1] : 0);
    if (tid < NBLK_SCAN) g_bsum[tid] = excl;
    if (tid == 0) g_rowstart[N_NODES] = E;
}

__global__ void distribute_kernel() {
    __shared__ int wsum[8];
    int tid = threadIdx.x, lane = tid & 31, wid = tid >> 5;
    int i = blockIdx.x * 256 + tid;
    int v = (i < N_NODES) ? g_deg[i] : 0;
    int s = v;
#pragma unroll
    for (int o = 1; o < 32; o <<= 1) {
        int t = __shfl_up_sync(0xffffffffu, s, o);
        if (lane >= o) s += t;
    }
    if (lane == 31) wsum[wid] = s;
    __syncthreads();
    if (wid == 0 && lane < 8) {
        int ws = wsum[lane];
        int ss = ws;
#pragma unroll
        for (int o = 1; o < 8; o <<= 1) {
            int t = __shfl_up_sync(0xffu, ss, o);
            if (lane >= o) ss += t;
        }
        wsum[lane] = ss;
    }
    __syncthreads();
    int excl = s - v + (wid ? wsum[wid - 1] : 0) + g_bsum[blockIdx.x];
    if (i < N_NODES) {
        g_rowstart[i] = excl;
        g_wptr[i] = excl;
    }
}

__global__ void fill_kernel(const void* __restrict__ edge, int E) {
    int e = blockIdx.x * blockDim.x + threadIdx.x;
    if (e >= E) return;
    int is64 = g_idx64;
    int s = load_idx(edge, e, is64);
    int d = load_idx(edge, (size_t)E + e, is64);
    int pos = atomicAdd(&g_wptr[d], 1);
    g_csr[pos] = s;
}

// ---------------- batch node selection ----------------
__global__ void mark_kernel(const void* __restrict__ idx, int B) {
    int r = blockIdx.x * blockDim.x + threadIdx.x;
    if (r >= B) return;
    int node = load_idx(idx, r, g_idx64);
    g_mark[node] = 1;
}

__global__ void compact_kernel() {
    int i = blockIdx.x * blockDim.x + threadIdx.x;
    if (i >= N_NODES) return;
    if (g_mark[i]) {
        int slot = atomicAdd(&g_nsel, 1);
        g_sel[slot] = i;
        g_node2slot[i] = slot;
    }
}

// ---------------- splits ----------------
__global__ void split_x_kernel(const float* __restrict__ x) {
    size_t i = (size_t)blockIdx.x * blockDim.x + threadIdx.x;
    const size_t n4 = (size_t)N_NODES * F_IN / 4;
    if (i >= n4) return;
    float4 v = reinterpret_cast<const float4*>(x)[i];
    split_store4(v, g_xh + i * 4, g_xl + i * 4);
}

__global__ void split_w_kernel(const float* __restrict__ W,
                               __nv_bfloat16* __restrict__ Th,
                               __nv_bfloat16* __restrict__ Tl, int K) {
    int idx = blockIdx.x * blockDim.x + threadIdx.x;
    if (idx >= K * 256) return;
    int k = idx >> 8;
    int n = idx & 255;
    __nv_bfloat16 h, l;
    split1(W[idx], h, l);
    Th[n * K + k] = h;
    Tl[n * K + k] = l;
}

// ---------------- layer-1 aggregate -> bf16 hi/lo (4-edge unroll) ----------------
__global__ __launch_bounds__(256) void agg1_kernel(const float* __restrict__ x) {
    int n = (int)(((size_t)blockIdx.x * blockDim.x + threadIdx.x) >> 5);
    if (n >= N_NODES) return;
    int lane = threadIdx.x & 31;
    int start = g_rowstart[n];
    int end = g_rowstart[n + 1];
    float4 acc0 = make_float4(0.f, 0.f, 0.f, 0.f);
    float4 acc1 = make_float4(0.f, 0.f, 0.f, 0.f);
    float4 acc2 = make_float4(0.f, 0.f, 0.f, 0.f);
    float4 acc3 = make_float4(0.f, 0.f, 0.f, 0.f);
    int e = start;
    for (; e + 3 < end; e += 4) {
        int s0 = g_csr[e];
        int s1 = g_csr[e + 1];
        int s2 = g_csr[e + 2];
        int s3 = g_csr[e + 3];
        float4 v0 = reinterpret_cast<const float4*>(x + (size_t)s0 * F_IN)[lane];
        float4 v1 = reinterpret_cast<const float4*>(x + (size_t)s1 * F_IN)[lane];
        float4 v2 = reinterpret_cast<const float4*>(x + (size_t)s2 * F_IN)[lane];
        float4 v3 = reinterpret_cast<const float4*>(x + (size_t)s3 * F_IN)[lane];
        acc0.x += v0.x; acc0.y += v0.y; acc0.z += v0.z; acc0.w += v0.w;
        acc1.x += v1.x; acc1.y += v1.y; acc1.z += v1.z; acc1.w += v1.w;
        acc2.x += v2.x; acc2.y += v2.y; acc2.z += v2.z; acc2.w += v2.w;
        acc3.x += v3.x; acc3.y += v3.y; acc3.z += v3.z; acc3.w += v3.w;
    }
    for (; e < end; e++) {
        int s0 = g_csr[e];
        float4 v0 = reinterpret_cast<const float4*>(x + (size_t)s0 * F_IN)[lane];
        acc0.x += v0.x; acc0.y += v0.y; acc0.z += v0.z; acc0.w += v0.w;
    }
    float r = 1.0f / fmaxf((float)(end - start), 1.0f);
    float4 o;
    o.x = (acc0.x + acc1.x + acc2.x + acc3.x) * r;
    o.y = (acc0.y + acc1.y + acc2.y + acc3.y) * r;
    o.z = (acc0.z + acc1.z + acc2.z + acc3.z) * r;
    o.w = (acc0.w + acc1.w + acc2.w + acc3.w) * r;
    size_t off = (size_t)n * F_IN + lane * 4;
    split_store4(o, g_a1h + off, g_a1l + off);
}

// ---------------- layer-2 aggregate (selected slots) -> bf16 hi/lo ----------------
__global__ __launch_bounds__(256) void agg2c_kernel() {
    int slot = (int)(((size_t)blockIdx.x * blockDim.x + threadIdx.x) >> 5);
    if (slot >= g_nsel) return;
    int n = g_sel[slot];
    int lane = threadIdx.x & 31;
    int start = g_rowstart[n];
    int end = g_rowstart[n + 1];
    float4 a0 = make_float4(0.f, 0.f, 0.f, 0.f);
    float4 a1 = make_float4(0.f, 0.f, 0.f, 0.f);
    for (int e = start; e < end; e++) {
        int s = g_csr[e];
        const float4* hp = reinterpret_cast<const float4*>(g_h1 + (size_t)s * HID);
        float4 v0 = hp[lane];
        float4 v1 = hp[lane + 32];
        a0.x += v0.x; a0.y += v0.y; a0.z += v0.z; a0.w += v0.w;
        a1.x += v1.x; a1.y += v1.y; a1.z += v1.z; a1.w += v1.w;
    }
    float r = 1.0f / fmaxf((float)(end - start), 1.0f);
    a0.x *= r; a0.y *= r; a0.z *= r; a0.w *= r;
    a1.x *= r; a1.y *= r; a1.z *= r; a1.w *= r;
    size_t off = (size_t)slot * HID;
    split_store4(a0, g_a2h + off + lane * 4, g_a2l + off + lane * 4);
    split_store4(a1, g_a2h + off + 128 + lane * 4, g_a2l + off + 128 + lane * 4);
}

// ---------------- bf16x2 tensor-core dual GEMM: cp.async double-buffer + ldmatrix ----------------
__device__ __forceinline__ void mma_bf16(float* c, const uint32_t* a, const uint32_t* b) {
    asm volatile(
        "mma.sync.aligned.m16n8k16.row.col.f32.bf16.bf16.f32 "
        "{%0,%1,%2,%3}, {%4,%5,%6,%7}, {%8,%9}, {%0,%1,%2,%3};"
        : "+f"(c[0]), "+f"(c[1]), "+f"(c[2]), "+f"(c[3])
        : "r"(a[0]), "r"(a[1]), "r"(a[2]), "r"(a[3]), "r"(b[0]), "r"(b[1]));
}

#define GROWB 80
#define GAB 10240
#define GBUFB 40960
#define GEMM_SMEM 81920

__global__ __launch_bounds__(256, 2) void gemm_dual_pre_kernel(
    const __nv_bfloat16* __restrict__ A0h, const __nv_bfloat16* __restrict__ A0l, int K0,
    const __nv_bfloat16* __restrict__ A1h, const __nv_bfloat16* __restrict__ A1l, int K1,
    const __nv_bfloat16* __restrict__ B0h, const __nv_bfloat16* __restrict__ B0l,
    const __nv_bfloat16* __restrict__ B1h, const __nv_bfloat16* __restrict__ B1l,
    const float* __restrict__ bias, float* __restrict__ C,
    __nv_bfloat16* __restrict__ Ch, __nv_bfloat16* __restrict__ Cl, int M) {
    const int N = 256;
    extern __shared__ char gsm[];
    uint32_t sbase = smem_to_u32(gsm);

    int tid = threadIdx.x;
    int lane = tid & 31;
    int wid = tid >> 5;
    int bm = blockIdx.x * 128;
    int bn = blockIdx.y * 128;
    int wm = (wid >> 2) * 64;
    int wn = (wid & 3) * 32;

    float acc[4][4][4];
#pragma unroll
    for (int mi = 0; mi < 4; mi++)
#pragma unroll
        for (int ni = 0; ni < 4; ni++)
#pragma unroll
            for (int q = 0; q < 4; q++) acc[mi][ni][q] = 0.f;

    int arow = tid >> 1;
    int ak0 = (tid & 1) * 16;
    int g = lane >> 2;
    int tq = (lane & 3) * 2;

    int lrA = lane & 15;
    int lcA = (lane >> 4) << 3;
    int lrBoff = ((lane >> 4) << 3) + (lane & 7);
    int lcB = ((lane >> 3) & 1) << 3;

    int K = K0 + K1;
    int T = K >> 5;

    int asz = (bm + arow < M) ? 16 : 0;
    uint32_t sA = sbase + arow * GROWB + ak0 * 2;
    uint32_t sB = sbase + 2 * GAB + arow * GROWB + ak0 * 2;

    auto issue = [&](int t, int buf) {
        const __nv_bfloat16 *pah, *pal, *pbh, *pbl;
        int lda, kloc;
        int kt = t << 5;
        if (kt < K0) { pah = A0h; pal = A0l; pbh = B0h; pbl = B0l; lda = K0; kloc = kt; }
        else         { pah = A1h; pal = A1l; pbh = B1h; pbl = B1l; lda = K1; kloc = kt - K0; }
        size_t aoff = (size_t)(bm + arow) * lda + kloc + ak0;
        size_t boff = (size_t)(bn + arow) * lda + kloc + ak0;
        uint32_t bofs = buf * GBUFB;
        cp_async16(sA + bofs, pah + aoff, asz);
        cp_async16(sA + bofs + 16, pah + aoff + 8, asz);
        cp_async16(sA + bofs + GAB, pal + aoff, asz);
        cp_async16(sA + bofs + GAB + 16, pal + aoff + 8, asz);
        cp_async16(sB + bofs, pbh + boff, 16);
        cp_async16(sB + bofs + 16, pbh + boff + 8, 16);
        cp_async16(sB + bofs + GAB, pbl + boff, 16);
        cp_async16(sB + bofs + GAB + 16, pbl + boff + 8, 16);
    };

    issue(0, 0); CP_COMMIT();
    if (T > 1) { issue(1, 1); CP_COMMIT(); }

    for (int t = 0; t < T; t++) {
        if (t == T - 1) { CP_WAIT0(); } else { CP_WAIT1(); }
        __syncthreads();

        int buf = t & 1;
        uint32_t bb = sbase + buf * GBUFB;
#pragma unroll
        for (int ks = 0; ks < 2; ks++) {
            int k0 = ks * 16;
            uint32_t bfh[4][2], bfl[4][2];
#pragma unroll
            for (int np = 0; np < 4; np += 2) {
                uint32_t aB = bb + 2 * GAB + (wn + np * 8 + lrBoff) * GROWB + (k0 + lcB) * 2;
                uint32_t r[4];
                ldsm_x4(r, aB);
                bfh[np][0] = r[0]; bfh[np][1] = r[1];
                bfh[np + 1][0] = r[2]; bfh[np + 1][1] = r[3];
                ldsm_x4(r, aB + GAB);
                bfl[np][0] = r[0]; bfl[np][1] = r[1];
                bfl[np + 1][0] = r[2]; bfl[np + 1][1] = r[3];
            }
            uint32_t aA = bb + (wm + lrA) * GROWB + (k0 + lcA) * 2;
#pragma unroll
            for (int mi = 0; mi < 4; mi++) {
                uint32_t ah[4], al[4];
                ldsm_x4(ah, aA + mi * (16 * GROWB));
                ldsm_x4(al, aA + GAB + mi * (16 * GROWB));
#pragma unroll
                for (int ni = 0; ni < 4; ni++) {
                    mma_bf16(acc[mi][ni], ah, bfh[ni]);
                    mma_bf16(acc[mi][ni], ah, bfl[ni]);
                    mma_bf16(acc[mi][ni], al, bfh[ni]);
                }
            }
        }
        __syncthreads();
        if (t + 2 < T) { issue(t + 2, buf); CP_COMMIT(); }
    }

#pragma unroll
    for (int mi = 0; mi < 4; mi++) {
#pragma unroll
        for (int ni = 0; ni < 4; ni++) {
            int col = bn + wn + ni * 8 + tq;
            float bv0 = bias[col];
            float bv1 = bias[col + 1];
#pragma unroll
            for (int h = 0; h < 2; h++) {
                int r = bm + wm + mi * 16 + g + h * 8;
                if (r < M) {
                    float v0 = fmaxf(acc[mi][ni][h * 2 + 0] + bv0, 0.f);
                    float v1 = fmaxf(acc[mi][ni][h * 2 + 1] + bv1, 0.f);
                    *reinterpret_cast<float2*>(&C[(size_t)r * N + col]) = make_float2(v0, v1);
                    if (Ch && g_mark[r]) {
                        int slot = g_node2slot[r];
                        __nv_bfloat16 h0, h1, l0, l1;
                        split1(v0, h0, l0);
                        split1(v1, h1, l1);
                        *reinterpret_cast<__nv_bfloat162*>(&Ch[(size_t)slot * N + col]) =
                            __halves2bfloat162(h0, h1);
                        *reinterpret_cast<__nv_bfloat162*>(&Cl[(size_t)slot * N + col]) =
                            __halves2bfloat162(l0, l1);
                    }
                }
            }
        }
    }
}

// ---------------- MLP head ----------------
__global__ __launch_bounds__(256) void mlp_kernel(
    const float* __restrict__ x_tab, const void* __restrict__ idx,
    const float* __restrict__ W1, const float* __restrict__ b1,
    const float* __restrict__ W2, const float* __restrict__ b2,
    const float* __restrict__ W3, const float* __restrict__ b3,
    float* __restrict__ out, int B) {
    __shared__ float zs[8][280];
    __shared__ float z1s[8][64];
    int w = threadIdx.x >> 5;
    int lane = threadIdx.x & 31;
    int row = blockIdx.x * 8 + w;
    if (row >= B) return;
    int node = load_idx(idx, row, g_idx64);
    int slot = g_node2slot[node];
    const float4* h = reinterpret_cast<const float4*>(g_h2c + (size_t)slot * HID);
    float4 v = h[lane];
    *reinterpret_cast<float4*>(&zs[w][lane * 4]) = v;
    v = h[lane + 32];
    *reinterpret_cast<float4*>(&zs[w][128 + lane * 4]) = v;
    if (lane < 16) zs[w][256 + lane] = x_tab[row * 16 + lane];
    __syncwarp();

    float a0 = b1[lane];
    float a1 = b1[lane + 32];
#pragma unroll 4
    for (int k = 0; k < 272; k++) {
        float zk = zs[w][k];
        a0 += zk * W1[k * 64 + lane];
        a1 += zk * W1[k * 64 + lane + 32];
    }
    z1s[w][lane] = fmaxf(a0, 0.f);
    z1s[w][lane + 32] = fmaxf(a1, 0.f);
    __syncwarp();

    float a = b2[lane];
#pragma unroll
    for (int k = 0; k < 64; k++) a += z1s[w][k] * W2[k * 32 + lane];
    float z2 = fmaxf(a, 0.f);

    float p = z2 * W3[lane];
#pragma unroll
    for (int off = 16; off; off >>= 1) p += __shfl_down_sync(0xffffffffu, p, off);
    if (lane == 0) out[row] = p + b3[0];
}

// ---------------- launch ----------------
extern "C" void kernel_launch(void* const* d_in, const int* in_sizes, int n_in,
                              void* d_out, int out_size) {
    const float* x     = (const float*)d_in[0];
    const void* edge   = d_in[1];
    const void* idxb   = d_in[2];
    const float* x_tab = (const float*)d_in[3];
    const float* Wl1 = (const float*)d_in[4];
    const float* bl1 = (const float*)d_in[5];
    const float* Wr1 = (const float*)d_in[6];
    const float* Wl2 = (const float*)d_in[7];
    const float* bl2 = (const float*)d_in[8];
    const float* Wr2 = (const float*)d_in[9];
    const float* W1  = (const float*)d_in[10];
    const float* b1  = (const float*)d_in[11];
    const float* W2  = (const float*)d_in[12];
    const float* b2  = (const float*)d_in[13];
    const float* W3  = (const float*)d_in[14];
    const float* b3  = (const float*)d_in[15];
    float* out = (float*)d_out;

    int E = in_sizes[1] / 2;
    if (E > E_MAX) E = E_MAX;
    int B = in_sizes[2];
    if (B > B_MAX) B = B_MAX;

    __nv_bfloat16 *p_xh, *p_xl, *p_a1h, *p_a1l, *p_h1ch, *p_h1cl, *p_a2h, *p_a2l;
    __nv_bfloat16 *p_wl1h, *p_wl1l, *p_wr1h, *p_wr1l, *p_wl2h, *p_wl2l, *p_wr2h, *p_wr2l;
    float *p_h1, *p_h2c;
    cudaGetSymbolAddress((void**)&p_xh, g_xh);
    cudaGetSymbolAddress((void**)&p_xl, g_xl);
    cudaGetSymbolAddress((void**)&p_a1h, g_a1h);
    cudaGetSymbolAddress((void**)&p_a1l, g_a1l);
    cudaGetSymbolAddress((void**)&p_h1, g_h1);
    cudaGetSymbolAddress((void**)&p_h1ch, g_h1ch);
    cudaGetSymbolAddress((void**)&p_h1cl, g_h1cl);
    cudaGetSymbolAddress((void**)&p_a2h, g_a2h);
    cudaGetSymbolAddress((void**)&p_a2l, g_a2l);
    cudaGetSymbolAddress((void**)&p_h2c, g_h2c);
    cudaGetSymbolAddress((void**)&p_wl1h, g_wl1h);
    cudaGetSymbolAddress((void**)&p_wl1l, g_wl1l);
    cudaGetSymbolAddress((void**)&p_wr1h, g_wr1h);
    cudaGetSymbolAddress((void**)&p_wr1l, g_wr1l);
    cudaGetSymbolAddress((void**)&p_wl2h, g_wl2h);
    cudaGetSymbolAddress((void**)&p_wl2l, g_wl2l);
    cudaGetSymbolAddress((void**)&p_wr2h, g_wr2h);
    cudaGetSymbolAddress((void**)&p_wr2l, g_wr2l);

    static cudaStream_t s1 = nullptr, s2 = nullptr;
    static cudaEvent_t ev_root = nullptr, ev_split = nullptr, ev_sel = nullptr;
    if (!s1) {
        cudaStreamCreateWithFlags(&s1, cudaStreamNonBlocking);
        cudaStreamCreateWithFlags(&s2, cudaStreamNonBlocking);
        cudaEventCreateWithFlags(&ev_root, cudaEventDisableTiming);
        cudaEventCreateWithFlags(&ev_split, cudaEventDisableTiming);
        cudaEventCreateWithFlags(&ev_sel, cudaEventDisableTiming);
        cudaFuncSetAttribute(gemm_dual_pre_kernel,
                             cudaFuncAttributeMaxDynamicSharedMemorySize, GEMM_SMEM);
    }

    // 0. sniff, then fork
    sniff_kernel<<<1, 32>>>((const int*)edge);
    cudaEventRecord(ev_root, 0);
    cudaStreamWaitEvent(s1, ev_root, 0);
    cudaStreamWaitEvent(s2, ev_root, 0);

    // branch A (default): CSR build
    zero_deg_mark_kernel<<<NBLK_SCAN, 256>>>();
    degree_kernel<<<(E + 255) / 256, 256>>>(edge, E);
    blocksum_kernel<<<NBLK_SCAN, 256>>>();
    scan_bsum_kernel<<<1, 512>>>(E);
    distribute_kernel<<<NBLK_SCAN, 256>>>();
    fill_kernel<<<(E + 255) / 256, 256>>>(edge, E);

    // branch B (s1): splits
    {
        size_t n4 = (size_t)N_NODES * F_IN / 4;
        split_x_kernel<<<(int)((n4 + 255) / 256), 256, 0, s1>>>(x);
        split_w_kernel<<<(F_IN * 256 + 255) / 256, 256, 0, s1>>>(Wl1, p_wl1h, p_wl1l, F_IN);
        split_w_kernel<<<(F_IN * 256 + 255) / 256, 256, 0, s1>>>(Wr1, p_wr1h, p_wr1l, F_IN);
        split_w_kernel<<<(HID * 256 + 255) / 256, 256, 0, s1>>>(Wl2, p_wl2h, p_wl2l, HID);
        split_w_kernel<<<(HID * 256 + 255) / 256, 256, 0, s1>>>(Wr2, p_wr2h, p_wr2l, HID);
        cudaEventRecord(ev_split, s1);
    }

    // branch C (s2): batch-node selection (mark/node2slot read by gemm1 epilogue)
    mark_kernel<<<(B + 255) / 256, 256, 0, s2>>>(idxb, B);
    compact_kernel<<<NBLK_SCAN, 256, 0, s2>>>();
    cudaEventRecord(ev_sel, s2);

    // default: layer-1 aggregate (needs CSR only)
    agg1_kernel<<<(N_NODES * 32 + 255) / 256, 256>>>(x);

    // join splits + selection, then gemm1 (fused compacted h1 split)
    cudaStreamWaitEvent(0, ev_split, 0);
    cudaStreamWaitEvent(0, ev_sel, 0);
    {
        dim3 grid((N_NODES + 127) / 128, 2);
        gemm_dual_pre_kernel<<<grid, 256, GEMM_SMEM>>>(
            p_a1h, p_a1l, F_IN, p_xh, p_xl, F_IN,
            p_wl1h, p_wl1l, p_wr1h, p_wr1l,
            bl1, p_h1, p_h1ch, p_h1cl, N_NODES);
    }

    // layer-2 aggregate (selected slots)
    agg2c_kernel<<<(B * 32 + 255) / 256, 256>>>();

    // gemm2 (selected slots)
    {
        dim3 grid((B + 127) / 128, 2);
        gemm_dual_pre_kernel<<<grid, 256, GEMM_SMEM>>>(
            p_a2h, p_a2l, HID, p_h1ch, p_h1cl, HID,
            p_wl2h, p_wl2l, p_wr2h, p_wr2l,
            bl2, p_h2c, (__nv_bfloat16*)nullptr, (__nv_bfloat16*)nullptr, B);
    }

    // MLP head
    mlp_kernel<<<(B + 7) / 8, 256>>>(x_tab, idxb, W1, b1, W2, b2, W3, b3, out, B);
}